// round 17
// baseline (speedup 1.0000x reference)
#include <cuda_runtime.h>
#include <cuda_fp16.h>
#include <cstdint>

#define NN 50000
#define NE 600000
#define NG 500
#define F  128

// ---------------- scratch (static __device__, no allocation) ----------------
__device__ __align__(16) __half g_T [NN * F];  // T' = (A@W)*dinv[row], fp16
__device__ __align__(16) __half g_X [NN * F];  // x converted to fp16
__device__ __align__(16) __half g_H0[NN * F];  // layer outputs (ping), post-relu, fp16
__device__ __align__(16) __half g_H1[NN * F];  // layer outputs (pong), post-relu, fp16
__device__ int   g_degi[NN];
__device__ float g_dinv[NN];
__device__ int   g_start[NN];
__device__ int   g_cur [NN];
__device__ int   g_csrc[NE];
__device__ __align__(16) float g_sums[NG * F];
__device__ int   g_cnt [NG];
__device__ int   g_e64;
__device__ int   g_b64;
// fp16 W fragments: [layer][nhalf][nt(8)][ks(8)][lane(32)][reg(2)] -> 8192 u32 per layer
__device__ __align__(16) uint32_t g_Wh[3 * 8192];
__device__ __align__(16) uint32_t g_Wl[3 * 8192];

// ---------------- init: dtype detect (strided probes) + zero everything ----------------
__global__ void k_init(const void* edge, const void* batch) {
    int t = threadIdx.x;
    int b = blockIdx.x;
    if (b == 0) {
        // probe edge src region, strided deep into the array
        __shared__ int bad;
        if (t == 0) bad = 0;
        __syncthreads();
        long long v = ((const long long*)edge)[(long long)t * 1171];   // < NE/2
        if (v < 0 || v >= NN) atomicOr(&bad, 1);
        __syncthreads();
        if (t == 0) g_e64 = !bad;
    } else if (b == 1) {
        __shared__ int bad;
        if (t == 0) bad = 0;
        __syncthreads();
        long long v = ((const long long*)batch)[(long long)t * 97];    // < NN/2
        if (v < 0 || v >= NG) atomicOr(&bad, 1);
        __syncthreads();
        if (t == 0) g_b64 = !bad;
    }
    int i = b * 256 + t;
    if (i < NN) g_degi[i] = 0;
    if (i < NG * F) g_sums[i] = 0.f;
    if (i < NG) g_cnt[i] = 0;
}

__device__ __forceinline__ int edge_at(const void* edge, long long idx) {
    return g_e64 ? (int)((const long long*)edge)[idx] : ((const int*)edge)[idx];
}
__device__ __forceinline__ int batch_at(const void* batch, int idx) {
    return g_b64 ? (int)((const long long*)batch)[idx] : ((const int*)batch)[idx];
}

// ---------------- degree ----------------
__global__ void k_deg(const void* __restrict__ edge) {
    int i = blockIdx.x * blockDim.x + threadIdx.x;
    if (i >= NE) return;
    int d = edge_at(edge, (long long)NE + i);
    atomicAdd(&g_degi[d], 1);
}

// ---------------- single-block scan: g_start/g_cur/g_dinv ----------------
#define CHUNK 49   // 1024*49 >= NN
__global__ void __launch_bounds__(1024) k_scan() {
    __shared__ int s[1024];
    int t = threadIdx.x;
    int beg = t * CHUNK;
    int end = min(beg + CHUNK, NN);
    int sum = 0;
    for (int i = beg; i < end; i++) sum += g_degi[i];
    s[t] = sum; __syncthreads();
#pragma unroll
    for (int off = 1; off < 1024; off <<= 1) {
        int x = (t >= off) ? s[t - off] : 0;
        __syncthreads();
        if (t >= off) s[t] += x;
        __syncthreads();
    }
    int run = s[t] - sum;     // exclusive prefix
    for (int i = beg; i < end; i++) {
        int d = g_degi[i];
        g_start[i] = run;
        g_cur[i] = run;
        g_dinv[i] = rsqrtf((float)(d + 1));
        run += d;
    }
}

// ---------------- CSR fill ----------------
__global__ void k_fill(const void* __restrict__ edge) {
    int i = blockIdx.x * blockDim.x + threadIdx.x;
    if (i >= NE) return;
    int s = edge_at(edge, i);
    int d = edge_at(edge, (long long)NE + i);
    int pos = atomicAdd(&g_cur[d], 1);
    g_csrc[pos] = s;
}

// ---------------- fused convert: W frags (blocks 0..95) + x->fp16 (rest) ----------------
// W frag e (per layer): ((NT*8 + ks)*32 + lane)*2 + j holds half2 {W[k][n], W[k+1][n]}
//   k = ks*16 + 2*(lane&3) + 8*j ; n = NT*8 + (lane>>2)
__global__ void k_convert(const float* __restrict__ x,
                          const float* __restrict__ W1,
                          const float* __restrict__ W2,
                          const float* __restrict__ W3) {
    int b = blockIdx.x;
    int t = threadIdx.x;
    if (b < 96) {
        int e = b * 256 + t;               // < 24576 = 3*8192
        int l = e / 8192;
        int f = e & 8191;
        const float* W = (l == 0) ? W1 : (l == 1 ? W2 : W3);
        int j  = f & 1;
        int ln = (f >> 1) & 31;
        int ks = (f >> 6) & 7;
        int NT = f >> 9;
        int k = ks * 16 + 2 * (ln & 3) + 8 * j;
        int n = NT * 8 + (ln >> 2);
        float v0 = W[k * 128 + n];
        float v1 = W[(k + 1) * 128 + n];
        __half h0 = __float2half_rn(v0);
        __half h1 = __float2half_rn(v1);
        __half l0 = __float2half_rn(v0 - __half2float(h0));
        __half l1 = __float2half_rn(v1 - __half2float(h1));
        uint32_t uh, ul;
        *(__half2*)&uh = __halves2half2(h0, h1);
        *(__half2*)&ul = __halves2half2(l0, l1);
        g_Wh[e] = uh;
        g_Wl[e] = ul;
    } else {
        int i = (b - 96) * 256 + t;        // < NN*F/4
        if (i >= NN * F / 4) return;
        float4 v = *(const float4*)(x + (size_t)i * 4);
        uint2 o;
        *(__half2*)&o.x = __floats2half2_rn(v.x, v.y);
        *(__half2*)&o.y = __floats2half2_rn(v.z, v.w);
        *(uint2*)(g_X + (size_t)i * 4) = o;
    }
}

// ---------------- fp16 mma ----------------
__device__ __forceinline__ void mma16(float* d, const uint32_t* a, uint32_t b0, uint32_t b1) {
    asm volatile(
        "mma.sync.aligned.m16n8k16.row.col.f32.f16.f16.f32 "
        "{%0,%1,%2,%3},{%4,%5,%6,%7},{%8,%9},{%0,%1,%2,%3};"
        : "+f"(d[0]), "+f"(d[1]), "+f"(d[2]), "+f"(d[3])
        : "r"(a[0]), "r"(a[1]), "r"(a[2]), "r"(a[3]), "r"(b0), "r"(b1));
}

// ---------------- tensor-core GEMM: g_T = (A_fp16 @ (Wh+Wl)) * dinv[row], fp16 out ----------
template<int SRC, int L>
__global__ void __launch_bounds__(512, 2) k_gemm_tc() {
    extern __shared__ uint32_t sb[];      // sWh[4096], sWl[4096]  (32 KB)
    uint32_t* sWh = sb;
    uint32_t* sWl = sb + 4096;
    const __half* A = (SRC == 0) ? g_X : (SRC == 1 ? g_H0 : g_H1);
    const int tid = threadIdx.x;
    const int nhalf = blockIdx.x & 1;
    const int mblk  = blockIdx.x >> 1;

    {
        const uint4* srcH = (const uint4*)(g_Wh + L * 8192 + nhalf * 4096);
        const uint4* srcL = (const uint4*)(g_Wl + L * 8192 + nhalf * 4096);
        uint4* dH = (uint4*)sWh;
        uint4* dL = (uint4*)sWl;
        for (int i = tid; i < 1024; i += 512) { dH[i] = srcH[i]; dL[i] = srcL[i]; }
    }
    __syncthreads();

    const int wid = tid >> 5, lane = tid & 31;
    const int g = lane >> 2, t4 = lane & 3;
    const int m_base = mblk * 256 + wid * 16;
    const int r0 = m_base + g, r1 = r0 + 8;
    const bool v0 = r0 < NN, v1 = r1 < NN;
    const __half* A0 = A + (size_t)r0 * 128;
    const __half* A1 = A + (size_t)r1 * 128;

    float acc[8][4];
#pragma unroll
    for (int nt = 0; nt < 8; nt++)
#pragma unroll
        for (int q = 0; q < 4; q++) acc[nt][q] = 0.f;

#pragma unroll
    for (int ks = 0; ks < 8; ks++) {
        const int k0 = ks * 16 + 2 * t4;
        uint32_t a[4];
        a[0] = v0 ? *(const uint32_t*)(A0 + k0)     : 0u;
        a[1] = v1 ? *(const uint32_t*)(A1 + k0)     : 0u;
        a[2] = v0 ? *(const uint32_t*)(A0 + k0 + 8) : 0u;
        a[3] = v1 ? *(const uint32_t*)(A1 + k0 + 8) : 0u;

#pragma unroll
        for (int nt = 0; nt < 8; nt++) {
            int base = ((nt * 8 + ks) * 32 + lane) * 2;
            uint32_t bh0 = sWh[base], bh1 = sWh[base + 1];
            uint32_t bl0 = sWl[base], bl1 = sWl[base + 1];
            mma16(acc[nt], a, bh0, bh1);
            mma16(acc[nt], a, bl0, bl1);
        }
    }

    float dv0 = v0 ? g_dinv[r0] : 0.f;
    float dv1 = v1 ? g_dinv[r1] : 0.f;
#pragma unroll
    for (int nt = 0; nt < 8; nt++) {
        int col = nhalf * 64 + nt * 8 + t4 * 2;
        if (v0) *(__half2*)(g_T + (size_t)r0 * 128 + col) =
            __floats2half2_rn(acc[nt][0] * dv0, acc[nt][1] * dv0);
        if (v1) *(__half2*)(g_T + (size_t)r1 * 128 + col) =
            __floats2half2_rn(acc[nt][2] * dv1, acc[nt][3] * dv1);
    }
}

// ---------------- gather: out[d] = relu(dinv[d]*(T'[d] + sum_e T'[src_e]) + b) ----------------
__device__ __forceinline__ void h4acc(float4& acc, uint2 h4) {
    float2 f0 = __half22float2(*(__half2*)&h4.x);
    float2 f1 = __half22float2(*(__half2*)&h4.y);
    acc.x += f0.x; acc.y += f0.y; acc.z += f1.x; acc.w += f1.y;
}

template<int DST, bool POOL>
__global__ void __launch_bounds__(256) k_gather(const float* __restrict__ b,
                                                const void* __restrict__ batch) {
    __half* O = (DST == 1) ? g_H0 : g_H1;
    int node = (blockIdx.x * blockDim.x + threadIdx.x) >> 5;
    int lane = threadIdx.x & 31;
    if (node >= NN) return;
    int c = lane * 4;
    const uint2* Tb = (const uint2*)g_T;   // 4 halves per uint2; row stride 32

    float4 acc = make_float4(0.f, 0.f, 0.f, 0.f);
    h4acc(acc, Tb[(size_t)node * 32 + lane]);          // self loop

    int e = g_start[node];
    int end = e + g_degi[node];
    // 8-way unrolled: batch index loads, then batch feature loads (MLP)
    for (; e + 8 <= end; e += 8) {
        int s0 = g_csrc[e],     s1 = g_csrc[e + 1], s2 = g_csrc[e + 2], s3 = g_csrc[e + 3];
        int s4 = g_csrc[e + 4], s5 = g_csrc[e + 5], s6 = g_csrc[e + 6], s7 = g_csrc[e + 7];
        uint2 v0 = Tb[(size_t)s0 * 32 + lane];
        uint2 v1 = Tb[(size_t)s1 * 32 + lane];
        uint2 v2 = Tb[(size_t)s2 * 32 + lane];
        uint2 v3 = Tb[(size_t)s3 * 32 + lane];
        uint2 v4 = Tb[(size_t)s4 * 32 + lane];
        uint2 v5 = Tb[(size_t)s5 * 32 + lane];
        uint2 v6 = Tb[(size_t)s6 * 32 + lane];
        uint2 v7 = Tb[(size_t)s7 * 32 + lane];
        h4acc(acc, v0); h4acc(acc, v1); h4acc(acc, v2); h4acc(acc, v3);
        h4acc(acc, v4); h4acc(acc, v5); h4acc(acc, v6); h4acc(acc, v7);
    }
    for (; e + 2 <= end; e += 2) {
        int s0 = g_csrc[e], s1 = g_csrc[e + 1];
        uint2 v0 = Tb[(size_t)s0 * 32 + lane];
        uint2 v1 = Tb[(size_t)s1 * 32 + lane];
        h4acc(acc, v0); h4acc(acc, v1);
    }
    for (; e < end; e++) h4acc(acc, Tb[(size_t)g_csrc[e] * 32 + lane]);

    float dv = g_dinv[node];
    float4 bb = *(const float4*)(b + c);
    acc.x = fmaxf(fmaf(acc.x, dv, bb.x), 0.f);
    acc.y = fmaxf(fmaf(acc.y, dv, bb.y), 0.f);
    acc.z = fmaxf(fmaf(acc.z, dv, bb.z), 0.f);
    acc.w = fmaxf(fmaf(acc.w, dv, bb.w), 0.f);

    if (POOL) {
        int gph = batch_at(batch, node);
        float* p = g_sums + gph * 128 + c;
        atomicAdd(p + 0, acc.x);
        atomicAdd(p + 1, acc.y);
        atomicAdd(p + 2, acc.z);
        atomicAdd(p + 3, acc.w);
        if (lane == 0) atomicAdd(&g_cnt[gph], 1);
    } else {
        uint2 o;
        *(__half2*)&o.x = __floats2half2_rn(acc.x, acc.y);
        *(__half2*)&o.y = __floats2half2_rn(acc.z, acc.w);
        *(uint2*)(O + (size_t)node * 128 + c) = o;
    }
}

// ---------------- head ----------------
__global__ void __launch_bounds__(64) k_head(const float* __restrict__ Wf1,
                                             const float* __restrict__ bf1,
                                             const float* __restrict__ Wf2,
                                             const float* __restrict__ bf2,
                                             float* __restrict__ out) {
    int g = blockIdx.x;
    int j = threadIdx.x;
    __shared__ float hg[128];
    __shared__ float red[2];
    float invc = 1.f / fmaxf((float)g_cnt[g], 1.f);
    for (int k = j; k < 128; k += 64) hg[k] = g_sums[g * 128 + k] * invc;
    __syncthreads();
    float acc = bf1[j];
#pragma unroll
    for (int k = 0; k < 128; k++) acc = fmaf(hg[k], Wf1[k * 64 + j], acc);
    acc = fmaxf(acc, 0.f) * Wf2[j];
#pragma unroll
    for (int off = 16; off; off >>= 1) acc += __shfl_down_sync(0xffffffffu, acc, off);
    if ((j & 31) == 0) red[j >> 5] = acc;
    __syncthreads();
    if (j == 0) out[g] = red[0] + red[1] + bf2[0];
}

// ---------------- launch ----------------
extern "C" void kernel_launch(void* const* d_in, const int* in_sizes, int n_in,
                              void* d_out, int out_size) {
    const float* x    = (const float*)d_in[0];
    const void*  edge = d_in[1];
    const void*  bat  = d_in[2];
    const float* W1 = (const float*)d_in[3];
    const float* b1 = (const float*)d_in[4];
    const float* W2 = (const float*)d_in[5];
    const float* b2 = (const float*)d_in[6];
    const float* W3 = (const float*)d_in[7];
    const float* b3 = (const float*)d_in[8];
    const float* Wf1 = (const float*)d_in[9];
    const float* bf1 = (const float*)d_in[10];
    const float* Wf2 = (const float*)d_in[11];
    const float* bf2 = (const float*)d_in[12];
    float* out = (float*)d_out;

    const int SMEM = 32768;   // sWh + sWl
    cudaFuncSetAttribute(k_gemm_tc<0, 0>, cudaFuncAttributeMaxDynamicSharedMemorySize, SMEM);
    cudaFuncSetAttribute(k_gemm_tc<1, 1>, cudaFuncAttributeMaxDynamicSharedMemorySize, SMEM);
    cudaFuncSetAttribute(k_gemm_tc<2, 2>, cudaFuncAttributeMaxDynamicSharedMemorySize, SMEM);

    const int TPB = 256;
    k_init<<<250, 256>>>(edge, bat);
    k_deg <<<(NE + TPB - 1) / TPB, TPB>>>(edge);
    k_scan<<<1, 1024>>>();
    k_fill<<<(NE + TPB - 1) / TPB, TPB>>>(edge);
    k_convert<<<96 + (NN * F / 4 + 255) / 256, 256>>>(x, W1, W2, W3);

    const int gemmGrid = 2 * ((NN + 255) / 256);   // 392
    const int gathGrid = (int)(((long long)NN * 32 + TPB - 1) / TPB);

    // layer 1: X -> H0
    k_gemm_tc<0, 0><<<gemmGrid, 512, SMEM>>>();
    k_gather<1, false><<<gathGrid, TPB>>>(b1, nullptr);
    // layer 2: H0 -> H1
    k_gemm_tc<1, 1><<<gemmGrid, 512, SMEM>>>();
    k_gather<2, false><<<gathGrid, TPB>>>(b2, nullptr);
    // layer 3: H1 -> (pool fused)
    k_gemm_tc<2, 2><<<gemmGrid, 512, SMEM>>>();
    k_gather<1, true><<<gathGrid, TPB>>>(b3, bat);

    k_head<<<NG, 64>>>(Wf1, bf1, Wf2, bf2, out);
}